// round 15
// baseline (speedup 1.0000x reference)
#include <cuda_runtime.h>
#include <cuda_bf16.h>
#include <math.h>
#include <stdint.h>

// Problem constants (fixed shapes from reference setup_inputs)
#define B_  8
#define L_  4096
#define D_  384
#define NH_ 8
#define NP_ 4
#define GRID_ 64
#define M_  (B_ * L_)    // 32768

#define NCHUNK 2
#define CHUNK_M (M_ / NCHUNK)        // 16384 rows = 4 batches (batch-aligned)

// ---------------- scratch (no cudaMalloc allowed) ----------------
__device__ float g_v[(size_t)M_ * D_];        // value @ Wv + bv (fp32)
__device__ float g_offwt[(size_t)M_ * 96];    // [off(64) | wt(32)] fp32
__device__ float g_attn[(size_t)M_ * D_];     // sampled, tf32-rounded
__device__ float g_wv32[D_ * D_];             // Wv tf32-rounded
__device__ float g_wo32[D_ * D_];             // Wo tf32-rounded
__device__ float g_wpk_hi[D_ * 96];           // packed [Woff|Wwt] tf32 hi
__device__ float g_wpk_lo[D_ * 96];           // packed [Woff|Wwt] tf32 lo
__device__ float g_bpk[96];                   // packed [boff|bwt]

__device__ __forceinline__ uint32_t f2tf32(float f) {
    uint32_t u;
    asm("cvt.rna.tf32.f32 %0, %1;" : "=r"(u) : "f"(f));
    return u;
}

// ---------------- tf32 conversion pre-pass ----------------
__global__ __launch_bounds__(256)
void cvt_tf32_kernel(const float4* __restrict__ in, float4* __restrict__ out, int n4) {
    int i = blockIdx.x * blockDim.x + threadIdx.x;
    int stride = gridDim.x * blockDim.x;
    for (; i < n4; i += stride) {
        float4 v = in[i];
        float4 o;
        o.x = __uint_as_float(f2tf32(v.x));
        o.y = __uint_as_float(f2tf32(v.y));
        o.z = __uint_as_float(f2tf32(v.z));
        o.w = __uint_as_float(f2tf32(v.w));
        out[i] = o;
    }
}

// ---------------- pack [Woff|Wwt] -> hi/lo tf32 split + bias pack ----------------
__global__ __launch_bounds__(256)
void pack_projw_kernel(const float* __restrict__ Woff, const float* __restrict__ boff,
                       const float* __restrict__ Wwt,  const float* __restrict__ bwt,
                       float* __restrict__ whi, float* __restrict__ wlo,
                       float* __restrict__ bpk) {
    int i = blockIdx.x * blockDim.x + threadIdx.x;
    int total = D_ * 96;
    for (; i < total; i += gridDim.x * blockDim.x) {
        int k = i / 96, c = i % 96;
        float w = (c < 64) ? Woff[k * 64 + c] : Wwt[k * 32 + (c - 64)];
        uint32_t h = f2tf32(w);
        whi[i] = __uint_as_float(h);
        wlo[i] = __uint_as_float(f2tf32(w - __uint_as_float(h)));
    }
    if (blockIdx.x == 0 && threadIdx.x < 96) {
        int c = threadIdx.x;
        bpk[c] = (c < 64) ? boff[c] : bwt[c - 64];
    }
}

// =====================================================================
// MMA + cp.async helpers
// =====================================================================
__device__ __forceinline__ void cp_async16(uint32_t saddr, const void* gptr) {
    asm volatile("cp.async.cg.shared.global [%0], [%1], 16;\n" :: "r"(saddr), "l"(gptr));
}
__device__ __forceinline__ void cp_commit() {
    asm volatile("cp.async.commit_group;\n" ::: "memory");
}
template <int N>
__device__ __forceinline__ void cp_wait() {
    asm volatile("cp.async.wait_group %0;\n" :: "n"(N) : "memory");
}

__device__ __forceinline__ void mma_tf32(float c[4], uint32_t a0, uint32_t a1,
                                         uint32_t a2, uint32_t a3,
                                         uint32_t b0, uint32_t b1) {
    asm volatile(
        "mma.sync.aligned.m16n8k8.row.col.f32.tf32.tf32.f32 "
        "{%0,%1,%2,%3}, {%4,%5,%6,%7}, {%8,%9}, {%0,%1,%2,%3};"
        : "+f"(c[0]), "+f"(c[1]), "+f"(c[2]), "+f"(c[3])
        : "r"(a0), "r"(a1), "r"(a2), "r"(a3), "r"(b0), "r"(b1));
}

// =====================================================================
// Shared GEMM tile geometry (R7)
// =====================================================================
#define BM_ 128
#define BN_ 128
#define BK_ 32
#define ASTR 36
#define BSTR 136
#define A_WORDS (BM_ * ASTR)
#define B_WORDS (BK_ * BSTR)
#define STAGE_WORDS (A_WORDS + B_WORDS)
#define NSTAGE 3
#define GEMM_SMEM_BYTES (NSTAGE * STAGE_WORDS * 4)
#define NK_ITERS (D_ / BK_)

// =====================================================================
// GEMM2: TF32 GEMM, 3-stage cp.async, A & W tf32 patterns. (R7)
// =====================================================================
__global__ __launch_bounds__(256, 2)
void gemm_tf32_kernel(const float* __restrict__ A,
                      const float* __restrict__ W,
                      const float* __restrict__ bias,
                      float* __restrict__ C,
                      int M, int N, int K) {
    extern __shared__ uint32_t smem[];

    const int tid  = threadIdx.x;
    const int lane = tid & 31;
    const int warp = tid >> 5;
    const int m0 = blockIdx.y * BM_;
    const int n0 = blockIdx.x * BN_;

    const int warp_m = warp >> 2;
    const int warp_n = warp & 3;
    const int mBase = warp_m * 64;
    const int nBase = warp_n * 32;
    const int qr = lane >> 2;
    const int qc = lane & 3;

    uint32_t smem_u32 = (uint32_t)__cvta_generic_to_shared((void*)smem);

    const int aRow0 = tid >> 3;
    const int aC16  = (tid & 7) * 16;
    const int bRow0 = tid >> 5;
    const int bC16  = (tid & 31) * 16;

    float acc[4][4][4];
    #pragma unroll
    for (int i = 0; i < 4; i++)
        #pragma unroll
        for (int j = 0; j < 4; j++)
            #pragma unroll
            for (int r = 0; r < 4; r++) acc[i][j][r] = 0.f;

    auto stage = [&](int k0, int buf) {
        uint32_t base = smem_u32 + buf * (STAGE_WORDS * 4);
        #pragma unroll
        for (int i = 0; i < 4; i++) {
            int arow = aRow0 + i * 32;
            cp_async16(base + arow * (ASTR * 4) + aC16,
                       A + (size_t)(m0 + arow) * K + k0 + (aC16 >> 2));
            int brow = bRow0 + i * 8;
            cp_async16(base + (A_WORDS * 4) + brow * (BSTR * 4) + bC16,
                       W + (size_t)(k0 + brow) * N + n0 + (bC16 >> 2));
        }
    };

    stage(0, 0); cp_commit();
    stage(BK_, 1); cp_commit();

    int buf = 0;
    for (int it = 0; it < NK_ITERS; it++) {
        cp_wait<1>();
        __syncthreads();

        if (it + 2 < NK_ITERS) {
            int nb = buf + 2; if (nb >= NSTAGE) nb -= NSTAGE;
            stage((it + 2) * BK_, nb);
        }
        cp_commit();

        const uint32_t* As = smem + buf * STAGE_WORDS;
        const uint32_t* Bs = As + A_WORDS;

        #pragma unroll
        for (int ks = 0; ks < 4; ks++) {
            const int kk = ks * 8;
            uint32_t b0[4], b1[4];
            #pragma unroll
            for (int nt = 0; nt < 4; nt++) {
                int col = nBase + nt * 8 + qr;
                b0[nt] = Bs[(kk + qc) * BSTR + col];
                b1[nt] = Bs[(kk + qc + 4) * BSTR + col];
            }
            #pragma unroll
            for (int mt = 0; mt < 4; mt++) {
                int row = mBase + mt * 16 + qr;
                int i00 = row * ASTR + kk + qc;
                int i10 = (row + 8) * ASTR + kk + qc;
                uint32_t a0 = As[i00], a1 = As[i10];
                uint32_t a2 = As[i00 + 4], a3 = As[i10 + 4];
                #pragma unroll
                for (int nt = 0; nt < 4; nt++) {
                    mma_tf32(acc[mt][nt], a0, a1, a2, a3, b0[nt], b1[nt]);
                }
            }
        }
        buf++; if (buf >= NSTAGE) buf = 0;
    }

    #pragma unroll
    for (int mt = 0; mt < 4; mt++) {
        int r0 = m0 + mBase + mt * 16 + qr;
        int r1 = r0 + 8;
        #pragma unroll
        for (int nt = 0; nt < 4; nt++) {
            int c0 = n0 + nBase + nt * 8 + 2 * qc;
            float bb0 = bias[c0], bb1 = bias[c0 + 1];
            float2 o0 = make_float2(acc[mt][nt][0] + bb0, acc[mt][nt][1] + bb1);
            float2 o1 = make_float2(acc[mt][nt][2] + bb0, acc[mt][nt][3] + bb1);
            *reinterpret_cast<float2*>(C + (size_t)r0 * N + c0) = o0;
            *reinterpret_cast<float2*>(C + (size_t)r1 * N + c0) = o1;
        }
    }
}

// =====================================================================
// GEMM1 (cvt-A): A fp32 -> tf32 at STS, register double-buffer;
// B via 3-stage cp.async. (R7)
// =====================================================================
#define CA_SMEM_BYTES ((2 * A_WORDS + 3 * B_WORDS) * 4)

__global__ __launch_bounds__(256, 2)
void gemm_cvtA_kernel(const float* __restrict__ A,
                      const float* __restrict__ W,
                      const float* __restrict__ bias,
                      float* __restrict__ C,
                      int M, int N, int K) {
    extern __shared__ uint32_t smem[];
    uint32_t* Asm = smem;
    uint32_t* Bsm = smem + 2 * A_WORDS;

    const int tid  = threadIdx.x;
    const int lane = tid & 31;
    const int warp = tid >> 5;
    const int m0 = blockIdx.y * BM_;
    const int n0 = blockIdx.x * BN_;

    const int warp_m = warp >> 2;
    const int warp_n = warp & 3;
    const int mBase = warp_m * 64;
    const int nBase = warp_n * 32;
    const int qr = lane >> 2;
    const int qc = lane & 3;

    uint32_t smemB_u32 = (uint32_t)__cvta_generic_to_shared((void*)Bsm);

    const int aRow0 = tid >> 3;
    const int aC4   = (tid & 7) * 4;
    const int bRow0 = tid >> 5;
    const int bC16  = (tid & 31) * 16;

    float4 aReg[4];

    auto gloadA = [&](int k0) {
        #pragma unroll
        for (int i = 0; i < 4; i++) {
            int arow = aRow0 + i * 32;
            aReg[i] = *reinterpret_cast<const float4*>(A + (size_t)(m0 + arow) * K + k0 + aC4);
        }
    };
    auto sstoreA = [&](int buf) {
        uint32_t* dst = Asm + buf * A_WORDS;
        #pragma unroll
        for (int i = 0; i < 4; i++) {
            int arow = aRow0 + i * 32;
            uint32_t* p = dst + arow * ASTR + aC4;
            p[0] = f2tf32(aReg[i].x);
            p[1] = f2tf32(aReg[i].y);
            p[2] = f2tf32(aReg[i].z);
            p[3] = f2tf32(aReg[i].w);
        }
    };
    auto stageB = [&](int k0, int buf) {
        uint32_t base = smemB_u32 + buf * (B_WORDS * 4);
        #pragma unroll
        for (int i = 0; i < 4; i++) {
            int brow = bRow0 + i * 8;
            cp_async16(base + brow * (BSTR * 4) + bC16,
                       W + (size_t)(k0 + brow) * N + n0 + (bC16 >> 2));
        }
    };

    float acc[4][4][4];
    #pragma unroll
    for (int i = 0; i < 4; i++)
        #pragma unroll
        for (int j = 0; j < 4; j++)
            #pragma unroll
            for (int r = 0; r < 4; r++) acc[i][j][r] = 0.f;

    gloadA(0);
    stageB(0, 0); cp_commit();
    stageB(BK_, 1); cp_commit();

    int bufB = 0;
    for (int it = 0; it < NK_ITERS; it++) {
        sstoreA(it & 1);
        if (it + 1 < NK_ITERS) gloadA((it + 1) * BK_);

        cp_wait<1>();
        __syncthreads();

        if (it + 2 < NK_ITERS) {
            int nb = bufB + 2; if (nb >= 3) nb -= 3;
            stageB((it + 2) * BK_, nb);
        }
        cp_commit();

        const uint32_t* As = Asm + (it & 1) * A_WORDS;
        const uint32_t* Bs = Bsm + bufB * B_WORDS;

        #pragma unroll
        for (int ks = 0; ks < 4; ks++) {
            const int kk = ks * 8;
            uint32_t b0[4], b1[4];
            #pragma unroll
            for (int nt = 0; nt < 4; nt++) {
                int col = nBase + nt * 8 + qr;
                b0[nt] = Bs[(kk + qc) * BSTR + col];
                b1[nt] = Bs[(kk + qc + 4) * BSTR + col];
            }
            #pragma unroll
            for (int mt = 0; mt < 4; mt++) {
                int row = mBase + mt * 16 + qr;
                int i00 = row * ASTR + kk + qc;
                int i10 = (row + 8) * ASTR + kk + qc;
                uint32_t a0 = As[i00], a1 = As[i10];
                uint32_t a2 = As[i00 + 4], a3 = As[i10 + 4];
                #pragma unroll
                for (int nt = 0; nt < 4; nt++) {
                    mma_tf32(acc[mt][nt], a0, a1, a2, a3, b0[nt], b1[nt]);
                }
            }
        }
        bufB++; if (bufB >= 3) bufB = 0;
    }

    #pragma unroll
    for (int mt = 0; mt < 4; mt++) {
        int r0 = m0 + mBase + mt * 16 + qr;
        int r1 = r0 + 8;
        #pragma unroll
        for (int nt = 0; nt < 4; nt++) {
            int c0 = n0 + nBase + nt * 8 + 2 * qc;
            float bb0 = bias[c0], bb1 = bias[c0 + 1];
            float2 o0 = make_float2(acc[mt][nt][0] + bb0, acc[mt][nt][1] + bb1);
            float2 o1 = make_float2(acc[mt][nt][2] + bb0, acc[mt][nt][3] + bb1);
            *reinterpret_cast<float2*>(C + (size_t)r0 * N + c0) = o0;
            *reinterpret_cast<float2*>(C + (size_t)r1 * N + c0) = o1;
        }
    }
}

// =====================================================================
// proj GEMM, 3xTF32 (near-fp32, unchanged from R7)
// =====================================================================
#define PBK 32
#define PJ_BM 128
#define PJ_ASTR 36
#define PJ_BSTR 100
#define PJ_A_WORDS (PJ_BM * PJ_ASTR)
#define PJ_B_WORDS (PBK * PJ_BSTR)
#define PJ_SMEM_BYTES ((2 * PJ_A_WORDS + 2 * PJ_B_WORDS) * 4)
#define PNK (D_ / PBK)

__global__ __launch_bounds__(256, 2)
void proj_gemm3x_kernel(const float* __restrict__ A,
                        const float* __restrict__ Whi,
                        const float* __restrict__ Wlo,
                        const float* __restrict__ bias,
                        float* __restrict__ C) {
    extern __shared__ uint32_t smemw[];
    uint32_t* Ahi = smemw;
    uint32_t* Alo = smemw + PJ_A_WORDS;
    uint32_t* Bhi = smemw + 2 * PJ_A_WORDS;
    uint32_t* Blo = smemw + 2 * PJ_A_WORDS + PJ_B_WORDS;

    const int tid  = threadIdx.x;
    const int lane = tid & 31;
    const int warp = tid >> 5;
    const int m0 = blockIdx.x * PJ_BM;

    const int warp_m = warp >> 2;
    const int warp_n = warp & 3;
    const int mBase = warp_m * 64;
    const int nBase = warp_n * 24;
    const int qr = lane >> 2;
    const int qc = lane & 3;

    const int aRow0 = tid >> 3;
    const int aC4   = (tid & 7) * 4;

    float4 aReg[4];
    float4 bhReg[3], blReg[3];

    auto gload = [&](int k0) {
        #pragma unroll
        for (int i = 0; i < 4; i++) {
            int arow = aRow0 + i * 32;
            aReg[i] = *reinterpret_cast<const float4*>(A + (size_t)(m0 + arow) * D_ + k0 + aC4);
        }
        #pragma unroll
        for (int i = 0; i < 3; i++) {
            int idx = tid + i * 256;
            int brow = idx / 24;
            int bc4  = (idx % 24) * 4;
            bhReg[i] = *reinterpret_cast<const float4*>(Whi + (size_t)(k0 + brow) * 96 + bc4);
            blReg[i] = *reinterpret_cast<const float4*>(Wlo + (size_t)(k0 + brow) * 96 + bc4);
        }
    };
    auto sstore = [&]() {
        #pragma unroll
        for (int i = 0; i < 4; i++) {
            int arow = aRow0 + i * 32;
            uint32_t* ph = Ahi + arow * PJ_ASTR + aC4;
            uint32_t* pl = Alo + arow * PJ_ASTR + aC4;
            float vv[4] = {aReg[i].x, aReg[i].y, aReg[i].z, aReg[i].w};
            #pragma unroll
            for (int j = 0; j < 4; j++) {
                uint32_t h = f2tf32(vv[j]);
                ph[j] = h;
                pl[j] = f2tf32(vv[j] - __uint_as_float(h));
            }
        }
        #pragma unroll
        for (int i = 0; i < 3; i++) {
            int idx = tid + i * 256;
            int brow = idx / 24;
            int bc4  = (idx % 24) * 4;
            *reinterpret_cast<float4*>(&Bhi[brow * PJ_BSTR + bc4]) = bhReg[i];
            *reinterpret_cast<float4*>(&Blo[brow * PJ_BSTR + bc4]) = blReg[i];
        }
    };

    float acc[4][3][4];
    #pragma unroll
    for (int i = 0; i < 4; i++)
        #pragma unroll
        for (int j = 0; j < 3; j++)
            #pragma unroll
            for (int r = 0; r < 4; r++) acc[i][j][r] = 0.f;

    gload(0);

    for (int it = 0; it < PNK; it++) {
        sstore();
        __syncthreads();
        if (it + 1 < PNK) gload((it + 1) * PBK);

        #pragma unroll
        for (int ks = 0; ks < 4; ks++) {
            const int kk = ks * 8;
            uint32_t bh0[3], bh1[3], bl0[3], bl1[3];
            #pragma unroll
            for (int nt = 0; nt < 3; nt++) {
                int col = nBase + nt * 8 + qr;
                bh0[nt] = Bhi[(kk + qc) * PJ_BSTR + col];
                bh1[nt] = Bhi[(kk + qc + 4) * PJ_BSTR + col];
                bl0[nt] = Blo[(kk + qc) * PJ_BSTR + col];
                bl1[nt] = Blo[(kk + qc + 4) * PJ_BSTR + col];
            }
            #pragma unroll
            for (int mt = 0; mt < 4; mt++) {
                int row = mBase + mt * 16 + qr;
                int i00 = row * PJ_ASTR + kk + qc;
                int i10 = (row + 8) * PJ_ASTR + kk + qc;
                uint32_t ah0 = Ahi[i00], ah1 = Ahi[i10];
                uint32_t ah2 = Ahi[i00 + 4], ah3 = Ahi[i10 + 4];
                uint32_t al0 = Alo[i00], al1 = Alo[i10];
                uint32_t al2 = Alo[i00 + 4], al3 = Alo[i10 + 4];
                #pragma unroll
                for (int nt = 0; nt < 3; nt++) {
                    mma_tf32(acc[mt][nt], ah0, ah1, ah2, ah3, bl0[nt], bl1[nt]);
                    mma_tf32(acc[mt][nt], al0, al1, al2, al3, bh0[nt], bh1[nt]);
                    mma_tf32(acc[mt][nt], ah0, ah1, ah2, ah3, bh0[nt], bh1[nt]);
                }
            }
        }
        __syncthreads();
    }

    #pragma unroll
    for (int mt = 0; mt < 4; mt++) {
        int r0 = m0 + mBase + mt * 16 + qr;
        int r1 = r0 + 8;
        #pragma unroll
        for (int nt = 0; nt < 3; nt++) {
            int c0 = nBase + nt * 8 + 2 * qc;
            float bb0 = bias[c0], bb1 = bias[c0 + 1];
            float2 o0 = make_float2(acc[mt][nt][0] + bb0, acc[mt][nt][1] + bb1);
            float2 o1 = make_float2(acc[mt][nt][2] + bb0, acc[mt][nt][3] + bb1);
            *reinterpret_cast<float2*>(C + (size_t)r0 * 96 + c0) = o0;
            *reinterpret_cast<float2*>(C + (size_t)r1 * 96 + c0) = o1;
        }
    }
}

// =====================================================================
// sampling: 16 rows per block (amortize setup), float4 gathers.
// Chunk-local (batch-aligned: 16 | 4096).
// =====================================================================
#define SROWS 16
__global__ __launch_bounds__(384)
void sample_kernel(const float* __restrict__ v,       // g_v chunk base
                   const float* __restrict__ offwt,   // chunk base
                   float4* __restrict__ attn) {       // chunk base
    __shared__ float row[SROWS][96];
    __shared__ int   sidx[SROWS][NH_][NP_][4];
    __shared__ float swg[SROWS][NH_][NP_][4];

    const int bl0 = blockIdx.x * SROWS;
    const int b = bl0 >> 12;
    const int t = threadIdx.x;

    // load 16 offwt rows (1536 floats, 4/thread)
    #pragma unroll
    for (int i = 0; i < 4; i++) {
        int k = t + i * 384;
        row[k / 96][k % 96] = offwt[(size_t)bl0 * 96 + k];
    }
    __syncthreads();

    // setup: 512 items (16 rows x 8 heads x 4 points), 2 passes
    #pragma unroll
    for (int pass = 0; pass < 2; pass++) {
        int item = t + pass * 384;
        if (item < SROWS * NH_ * NP_) {
            const int r  = item >> 5;
            const int hp = item & 31;
            const int hh = hp >> 2;
            const int p  = hp & 3;

            float lg[NP_];
            float m = -1e30f;
            #pragma unroll
            for (int q = 0; q < NP_; q++) { lg[q] = row[r][64 + hh * NP_ + q]; m = fmaxf(m, lg[q]); }
            float ssum = 0.f;
            #pragma unroll
            for (int q = 0; q < NP_; q++) ssum += __expf(lg[q] - m);
            const float s = __expf(lg[p] - m) / ssum;

            const int l = (bl0 + r) & (L_ - 1);
            const float off0 = row[r][hh * (NP_ * 2) + p * 2 + 0];
            const float off1 = row[r][hh * (NP_ * 2) + p * 2 + 1];
            const float gx = (float)(l & (GRID_ - 1)) * (1.f / (GRID_ - 1));
            const float gy = (float)(l >> 6)          * (1.f / (GRID_ - 1));
            const float ph = fminf(fmaxf(gx + off0, 0.f), 1.f) * (float)(GRID_ - 1);
            const float pw = fminf(fmaxf(gy + off1, 0.f), 1.f) * (float)(GRID_ - 1);
            const float y0f = floorf(ph), x0f = floorf(pw);
            const float wy = ph - y0f,    wx = pw - x0f;
            const int y0 = (int)y0f, x0 = (int)x0f;
            const int y1 = min(y0 + 1, GRID_ - 1);
            const int x1 = min(x0 + 1, GRID_ - 1);
            sidx[r][hh][p][0] = y0 * GRID_ + x0;  swg[r][hh][p][0] = s * (1.f - wy) * (1.f - wx);
            sidx[r][hh][p][1] = y0 * GRID_ + x1;  swg[r][hh][p][1] = s * (1.f - wy) * wx;
            sidx[r][hh][p][2] = y1 * GRID_ + x0;  swg[r][hh][p][2] = s * wy * (1.f - wx);
            sidx[r][hh][p][3] = y1 * GRID_ + x1;  swg[r][hh][p][3] = s * wy * wx;
        }
    }
    __syncthreads();

    const int r0 = t / 96;          // 0..3
    const int c4 = t % 96;
    const int hh = c4 / 12;
    const int d4 = c4 % 12;

    const float4* vb = reinterpret_cast<const float4*>(v) + (size_t)b * L_ * 96 + hh * 12 + d4;

    #pragma unroll
    for (int rr = 0; rr < 4; rr++) {
        const int r = r0 + rr * 4;
        float4 acc = make_float4(0.f, 0.f, 0.f, 0.f);
        #pragma unroll
        for (int p = 0; p < NP_; p++) {
            #pragma unroll
            for (int c = 0; c < 4; c++) {
                const float w = swg[r][hh][p][c];
                const float4 vv = vb[(size_t)sidx[r][hh][p][c] * 96];
                acc.x += w * vv.x;
                acc.y += w * vv.y;
                acc.z += w * vv.z;
                acc.w += w * vv.w;
            }
        }
        float4 o;
        o.x = __uint_as_float(f2tf32(acc.x));
        o.y = __uint_as_float(f2tf32(acc.y));
        o.z = __uint_as_float(f2tf32(acc.z));
        o.w = __uint_as_float(f2tf32(acc.w));
        attn[(size_t)(bl0 + r) * 96 + c4] = o;
    }
}

// ---------------- streams/events (host-side only; created pre-main) ----------------
struct AsyncCtx {
    cudaStream_t sB = nullptr, sC = nullptr;
    cudaEvent_t evRoot = nullptr, evProj = nullptr, evWv = nullptr;
    cudaEvent_t evG1[NCHUNK] = {}, evS[NCHUNK] = {};
    AsyncCtx() {
        cudaStreamCreateWithFlags(&sB, cudaStreamNonBlocking);
        cudaStreamCreateWithFlags(&sC, cudaStreamNonBlocking);
        cudaEventCreateWithFlags(&evRoot, cudaEventDisableTiming);
        cudaEventCreateWithFlags(&evProj, cudaEventDisableTiming);
        cudaEventCreateWithFlags(&evWv, cudaEventDisableTiming);
        for (int i = 0; i < NCHUNK; i++) {
            cudaEventCreateWithFlags(&evG1[i], cudaEventDisableTiming);
            cudaEventCreateWithFlags(&evS[i], cudaEventDisableTiming);
        }
    }
};
static AsyncCtx g_async;

// ---------------- launch ----------------
extern "C" void kernel_launch(void* const* d_in, const int* in_sizes, int n_in,
                              void* d_out, int out_size) {
    const float* query = (const float*)d_in[0];
    const float* value = (const float*)d_in[2];
    const float* Wv   = (const float*)d_in[7];
    const float* bv   = (const float*)d_in[8];
    const float* Woff = (const float*)d_in[9];
    const float* boff = (const float*)d_in[10];
    const float* Wwt  = (const float*)d_in[11];
    const float* bwt  = (const float*)d_in[12];
    const float* Wo   = (const float*)d_in[13];
    const float* bo   = (const float*)d_in[14];
    float* out = (float*)d_out;

    float *gv, *gow, *gat, *gwv, *gwo, *gwh, *gwl, *gbp;
    cudaGetSymbolAddress((void**)&gv,  g_v);
    cudaGetSymbolAddress((void**)&gow, g_offwt);
    cudaGetSymbolAddress((void**)&gat, g_attn);
    cudaGetSymbolAddress((void**)&gwv, g_wv32);
    cudaGetSymbolAddress((void**)&gwo, g_wo32);
    cudaGetSymbolAddress((void**)&gwh, g_wpk_hi);
    cudaGetSymbolAddress((void**)&gwl, g_wpk_lo);
    cudaGetSymbolAddress((void**)&gbp, g_bpk);

    cudaFuncSetAttribute(gemm_tf32_kernel,
                         cudaFuncAttributeMaxDynamicSharedMemorySize, GEMM_SMEM_BYTES);
    cudaFuncSetAttribute(gemm_cvtA_kernel,
                         cudaFuncAttributeMaxDynamicSharedMemorySize, CA_SMEM_BYTES);
    cudaFuncSetAttribute(proj_gemm3x_kernel,
                         cudaFuncAttributeMaxDynamicSharedMemorySize, PJ_SMEM_BYTES);

    // ---- fork point ----
    cudaEventRecord(g_async.evRoot, 0);
    cudaStreamWaitEvent(g_async.sB, g_async.evRoot, 0);
    cudaStreamWaitEvent(g_async.sC, g_async.evRoot, 0);

    // ---- stream B (idle until sample): Wv cvt off the critical path ----
    cvt_tf32_kernel<<<72, 256, 0, g_async.sB>>>((const float4*)Wv, (float4*)gwv, (D_ * D_) / 4);
    cudaEventRecord(g_async.evWv, g_async.sB);

    // ---- stream C: proj path + Wo cvt ----
    pack_projw_kernel<<<144, 256, 0, g_async.sC>>>(Woff, boff, Wwt, bwt, gwh, gwl, gbp);
    proj_gemm3x_kernel<<<M_ / PJ_BM, 256, PJ_SMEM_BYTES, g_async.sC>>>(query, gwh, gwl, gbp, gow);
    cvt_tf32_kernel<<<72, 256, 0, g_async.sC>>>((const float4*)Wo, (float4*)gwo, (D_ * D_) / 4);
    cudaEventRecord(g_async.evProj, g_async.sC);

    // ---- stream 0: G1 per chunk (waits Wv cvt) ----
    cudaStreamWaitEvent(0, g_async.evWv, 0);
    {
        dim3 grid(D_ / BN_, CHUNK_M / BM_);   // (3, 128) = 384 CTAs per chunk
        for (int i = 0; i < NCHUNK; i++) {
            size_t off = (size_t)i * CHUNK_M * D_;
            gemm_cvtA_kernel<<<grid, 256, CA_SMEM_BYTES>>>(value + off, gwv, bv, gv + off,
                                                           CHUNK_M, D_, D_);
            cudaEventRecord(g_async.evG1[i], 0);
        }
    }

    // ---- stream B: sample per chunk ----
    cudaStreamWaitEvent(g_async.sB, g_async.evProj, 0);
    for (int i = 0; i < NCHUNK; i++) {
        cudaStreamWaitEvent(g_async.sB, g_async.evG1[i], 0);
        size_t voff = (size_t)i * CHUNK_M * D_;
        size_t ooff = (size_t)i * CHUNK_M * 96;
        sample_kernel<<<CHUNK_M / SROWS, 384, 0, g_async.sB>>>(gv + voff, gow + ooff,
                                                               (float4*)(gat + voff));
        cudaEventRecord(g_async.evS[i], g_async.sB);
    }

    // ---- stream 0: G2 per chunk; joins all branches ----
    {
        dim3 grid(D_ / BN_, CHUNK_M / BM_);
        for (int i = 0; i < NCHUNK; i++) {
            cudaStreamWaitEvent(0, g_async.evS[i], 0);
            size_t off = (size_t)i * CHUNK_M * D_;
            gemm_tf32_kernel<<<grid, 256, GEMM_SMEM_BYTES>>>(gat + off, gwo, bo, out + off,
                                                             CHUNK_M, D_, D_);
        }
    }
}

// round 16
// speedup vs baseline: 1.0087x; 1.0087x over previous
#include <cuda_runtime.h>
#include <cuda_bf16.h>
#include <math.h>
#include <stdint.h>

// Problem constants (fixed shapes from reference setup_inputs)
#define B_  8
#define L_  4096
#define D_  384
#define NH_ 8
#define NP_ 4
#define GRID_ 64
#define M_  (B_ * L_)    // 32768

#define NCHUNK 2
#define CHUNK_M (M_ / NCHUNK)        // 16384 rows = 4 batches (batch-aligned)

// ---------------- scratch (no cudaMalloc allowed) ----------------
__device__ float g_v[(size_t)M_ * D_];        // value @ Wv + bv (fp32)
__device__ float g_offwt[(size_t)M_ * 96];    // [off(64) | wt(32)] fp32
__device__ float g_attn[(size_t)M_ * D_];     // sampled, tf32-rounded
__device__ float g_wv32[D_ * D_];             // Wv tf32-rounded
__device__ float g_wo32[D_ * D_];             // Wo tf32-rounded
__device__ float g_wpk_hi[D_ * 96];           // packed [Woff|Wwt] tf32 hi
__device__ float g_wpk_lo[D_ * 96];           // packed [Woff|Wwt] tf32 lo
__device__ float g_bpk[96];                   // packed [boff|bwt]

__device__ __forceinline__ uint32_t f2tf32(float f) {
    uint32_t u;
    asm("cvt.rna.tf32.f32 %0, %1;" : "=r"(u) : "f"(f));
    return u;
}

// ---------------- tf32 conversion pre-pass ----------------
__global__ __launch_bounds__(256)
void cvt_tf32_kernel(const float4* __restrict__ in, float4* __restrict__ out, int n4) {
    int i = blockIdx.x * blockDim.x + threadIdx.x;
    int stride = gridDim.x * blockDim.x;
    for (; i < n4; i += stride) {
        float4 v = in[i];
        float4 o;
        o.x = __uint_as_float(f2tf32(v.x));
        o.y = __uint_as_float(f2tf32(v.y));
        o.z = __uint_as_float(f2tf32(v.z));
        o.w = __uint_as_float(f2tf32(v.w));
        out[i] = o;
    }
}

// ---------------- pack [Woff|Wwt] -> hi/lo tf32 split + bias pack ----------------
__global__ __launch_bounds__(256)
void pack_projw_kernel(const float* __restrict__ Woff, const float* __restrict__ boff,
                       const float* __restrict__ Wwt,  const float* __restrict__ bwt,
                       float* __restrict__ whi, float* __restrict__ wlo,
                       float* __restrict__ bpk) {
    int i = blockIdx.x * blockDim.x + threadIdx.x;
    int total = D_ * 96;
    for (; i < total; i += gridDim.x * blockDim.x) {
        int k = i / 96, c = i % 96;
        float w = (c < 64) ? Woff[k * 64 + c] : Wwt[k * 32 + (c - 64)];
        uint32_t h = f2tf32(w);
        whi[i] = __uint_as_float(h);
        wlo[i] = __uint_as_float(f2tf32(w - __uint_as_float(h)));
    }
    if (blockIdx.x == 0 && threadIdx.x < 96) {
        int c = threadIdx.x;
        bpk[c] = (c < 64) ? boff[c] : bwt[c - 64];
    }
}

// =====================================================================
// MMA + cp.async helpers
// =====================================================================
__device__ __forceinline__ void cp_async16(uint32_t saddr, const void* gptr) {
    asm volatile("cp.async.cg.shared.global [%0], [%1], 16;\n" :: "r"(saddr), "l"(gptr));
}
__device__ __forceinline__ void cp_commit() {
    asm volatile("cp.async.commit_group;\n" ::: "memory");
}
template <int N>
__device__ __forceinline__ void cp_wait() {
    asm volatile("cp.async.wait_group %0;\n" :: "n"(N) : "memory");
}

__device__ __forceinline__ void mma_tf32(float c[4], uint32_t a0, uint32_t a1,
                                         uint32_t a2, uint32_t a3,
                                         uint32_t b0, uint32_t b1) {
    asm volatile(
        "mma.sync.aligned.m16n8k8.row.col.f32.tf32.tf32.f32 "
        "{%0,%1,%2,%3}, {%4,%5,%6,%7}, {%8,%9}, {%0,%1,%2,%3};"
        : "+f"(c[0]), "+f"(c[1]), "+f"(c[2]), "+f"(c[3])
        : "r"(a0), "r"(a1), "r"(a2), "r"(a3), "r"(b0), "r"(b1));
}

// =====================================================================
// Shared GEMM tile geometry (R7)
// =====================================================================
#define BM_ 128
#define BN_ 128
#define BK_ 32
#define ASTR 36
#define BSTR 136
#define A_WORDS (BM_ * ASTR)
#define B_WORDS (BK_ * BSTR)
#define STAGE_WORDS (A_WORDS + B_WORDS)
#define NSTAGE 3
#define GEMM_SMEM_BYTES (NSTAGE * STAGE_WORDS * 4)
#define NK_ITERS (D_ / BK_)

// =====================================================================
// GEMM2: TF32 GEMM, 3-stage cp.async, A & W tf32 patterns. (R7)
// =====================================================================
__global__ __launch_bounds__(256, 2)
void gemm_tf32_kernel(const float* __restrict__ A,
                      const float* __restrict__ W,
                      const float* __restrict__ bias,
                      float* __restrict__ C,
                      int M, int N, int K) {
    extern __shared__ uint32_t smem[];

    const int tid  = threadIdx.x;
    const int lane = tid & 31;
    const int warp = tid >> 5;
    const int m0 = blockIdx.y * BM_;
    const int n0 = blockIdx.x * BN_;

    const int warp_m = warp >> 2;
    const int warp_n = warp & 3;
    const int mBase = warp_m * 64;
    const int nBase = warp_n * 32;
    const int qr = lane >> 2;
    const int qc = lane & 3;

    uint32_t smem_u32 = (uint32_t)__cvta_generic_to_shared((void*)smem);

    const int aRow0 = tid >> 3;
    const int aC16  = (tid & 7) * 16;
    const int bRow0 = tid >> 5;
    const int bC16  = (tid & 31) * 16;

    float acc[4][4][4];
    #pragma unroll
    for (int i = 0; i < 4; i++)
        #pragma unroll
        for (int j = 0; j < 4; j++)
            #pragma unroll
            for (int r = 0; r < 4; r++) acc[i][j][r] = 0.f;

    auto stage = [&](int k0, int buf) {
        uint32_t base = smem_u32 + buf * (STAGE_WORDS * 4);
        #pragma unroll
        for (int i = 0; i < 4; i++) {
            int arow = aRow0 + i * 32;
            cp_async16(base + arow * (ASTR * 4) + aC16,
                       A + (size_t)(m0 + arow) * K + k0 + (aC16 >> 2));
            int brow = bRow0 + i * 8;
            cp_async16(base + (A_WORDS * 4) + brow * (BSTR * 4) + bC16,
                       W + (size_t)(k0 + brow) * N + n0 + (bC16 >> 2));
        }
    };

    stage(0, 0); cp_commit();
    stage(BK_, 1); cp_commit();

    int buf = 0;
    for (int it = 0; it < NK_ITERS; it++) {
        cp_wait<1>();
        __syncthreads();

        if (it + 2 < NK_ITERS) {
            int nb = buf + 2; if (nb >= NSTAGE) nb -= NSTAGE;
            stage((it + 2) * BK_, nb);
        }
        cp_commit();

        const uint32_t* As = smem + buf * STAGE_WORDS;
        const uint32_t* Bs = As + A_WORDS;

        #pragma unroll
        for (int ks = 0; ks < 4; ks++) {
            const int kk = ks * 8;
            uint32_t b0[4], b1[4];
            #pragma unroll
            for (int nt = 0; nt < 4; nt++) {
                int col = nBase + nt * 8 + qr;
                b0[nt] = Bs[(kk + qc) * BSTR + col];
                b1[nt] = Bs[(kk + qc + 4) * BSTR + col];
            }
            #pragma unroll
            for (int mt = 0; mt < 4; mt++) {
                int row = mBase + mt * 16 + qr;
                int i00 = row * ASTR + kk + qc;
                int i10 = (row + 8) * ASTR + kk + qc;
                uint32_t a0 = As[i00], a1 = As[i10];
                uint32_t a2 = As[i00 + 4], a3 = As[i10 + 4];
                #pragma unroll
                for (int nt = 0; nt < 4; nt++) {
                    mma_tf32(acc[mt][nt], a0, a1, a2, a3, b0[nt], b1[nt]);
                }
            }
        }
        buf++; if (buf >= NSTAGE) buf = 0;
    }

    #pragma unroll
    for (int mt = 0; mt < 4; mt++) {
        int r0 = m0 + mBase + mt * 16 + qr;
        int r1 = r0 + 8;
        #pragma unroll
        for (int nt = 0; nt < 4; nt++) {
            int c0 = n0 + nBase + nt * 8 + 2 * qc;
            float bb0 = bias[c0], bb1 = bias[c0 + 1];
            float2 o0 = make_float2(acc[mt][nt][0] + bb0, acc[mt][nt][1] + bb1);
            float2 o1 = make_float2(acc[mt][nt][2] + bb0, acc[mt][nt][3] + bb1);
            *reinterpret_cast<float2*>(C + (size_t)r0 * N + c0) = o0;
            *reinterpret_cast<float2*>(C + (size_t)r1 * N + c0) = o1;
        }
    }
}

// =====================================================================
// GEMM1 (cvt-A): A fp32 -> tf32 at STS, register double-buffer;
// B via 3-stage cp.async. (R7)
// =====================================================================
#define CA_SMEM_BYTES ((2 * A_WORDS + 3 * B_WORDS) * 4)

__global__ __launch_bounds__(256, 2)
void gemm_cvtA_kernel(const float* __restrict__ A,
                      const float* __restrict__ W,
                      const float* __restrict__ bias,
                      float* __restrict__ C,
                      int M, int N, int K) {
    extern __shared__ uint32_t smem[];
    uint32_t* Asm = smem;
    uint32_t* Bsm = smem + 2 * A_WORDS;

    const int tid  = threadIdx.x;
    const int lane = tid & 31;
    const int warp = tid >> 5;
    const int m0 = blockIdx.y * BM_;
    const int n0 = blockIdx.x * BN_;

    const int warp_m = warp >> 2;
    const int warp_n = warp & 3;
    const int mBase = warp_m * 64;
    const int nBase = warp_n * 32;
    const int qr = lane >> 2;
    const int qc = lane & 3;

    uint32_t smemB_u32 = (uint32_t)__cvta_generic_to_shared((void*)Bsm);

    const int aRow0 = tid >> 3;
    const int aC4   = (tid & 7) * 4;
    const int bRow0 = tid >> 5;
    const int bC16  = (tid & 31) * 16;

    float4 aReg[4];

    auto gloadA = [&](int k0) {
        #pragma unroll
        for (int i = 0; i < 4; i++) {
            int arow = aRow0 + i * 32;
            aReg[i] = *reinterpret_cast<const float4*>(A + (size_t)(m0 + arow) * K + k0 + aC4);
        }
    };
    auto sstoreA = [&](int buf) {
        uint32_t* dst = Asm + buf * A_WORDS;
        #pragma unroll
        for (int i = 0; i < 4; i++) {
            int arow = aRow0 + i * 32;
            uint32_t* p = dst + arow * ASTR + aC4;
            p[0] = f2tf32(aReg[i].x);
            p[1] = f2tf32(aReg[i].y);
            p[2] = f2tf32(aReg[i].z);
            p[3] = f2tf32(aReg[i].w);
        }
    };
    auto stageB = [&](int k0, int buf) {
        uint32_t base = smemB_u32 + buf * (B_WORDS * 4);
        #pragma unroll
        for (int i = 0; i < 4; i++) {
            int brow = bRow0 + i * 8;
            cp_async16(base + brow * (BSTR * 4) + bC16,
                       W + (size_t)(k0 + brow) * N + n0 + (bC16 >> 2));
        }
    };

    float acc[4][4][4];
    #pragma unroll
    for (int i = 0; i < 4; i++)
        #pragma unroll
        for (int j = 0; j < 4; j++)
            #pragma unroll
            for (int r = 0; r < 4; r++) acc[i][j][r] = 0.f;

    gloadA(0);
    stageB(0, 0); cp_commit();
    stageB(BK_, 1); cp_commit();

    int bufB = 0;
    for (int it = 0; it < NK_ITERS; it++) {
        sstoreA(it & 1);
        if (it + 1 < NK_ITERS) gloadA((it + 1) * BK_);

        cp_wait<1>();
        __syncthreads();

        if (it + 2 < NK_ITERS) {
            int nb = bufB + 2; if (nb >= 3) nb -= 3;
            stageB((it + 2) * BK_, nb);
        }
        cp_commit();

        const uint32_t* As = Asm + (it & 1) * A_WORDS;
        const uint32_t* Bs = Bsm + bufB * B_WORDS;

        #pragma unroll
        for (int ks = 0; ks < 4; ks++) {
            const int kk = ks * 8;
            uint32_t b0[4], b1[4];
            #pragma unroll
            for (int nt = 0; nt < 4; nt++) {
                int col = nBase + nt * 8 + qr;
                b0[nt] = Bs[(kk + qc) * BSTR + col];
                b1[nt] = Bs[(kk + qc + 4) * BSTR + col];
            }
            #pragma unroll
            for (int mt = 0; mt < 4; mt++) {
                int row = mBase + mt * 16 + qr;
                int i00 = row * ASTR + kk + qc;
                int i10 = (row + 8) * ASTR + kk + qc;
                uint32_t a0 = As[i00], a1 = As[i10];
                uint32_t a2 = As[i00 + 4], a3 = As[i10 + 4];
                #pragma unroll
                for (int nt = 0; nt < 4; nt++) {
                    mma_tf32(acc[mt][nt], a0, a1, a2, a3, b0[nt], b1[nt]);
                }
            }
        }
        bufB++; if (bufB >= 3) bufB = 0;
    }

    #pragma unroll
    for (int mt = 0; mt < 4; mt++) {
        int r0 = m0 + mBase + mt * 16 + qr;
        int r1 = r0 + 8;
        #pragma unroll
        for (int nt = 0; nt < 4; nt++) {
            int c0 = n0 + nBase + nt * 8 + 2 * qc;
            float bb0 = bias[c0], bb1 = bias[c0 + 1];
            float2 o0 = make_float2(acc[mt][nt][0] + bb0, acc[mt][nt][1] + bb1);
            float2 o1 = make_float2(acc[mt][nt][2] + bb0, acc[mt][nt][3] + bb1);
            *reinterpret_cast<float2*>(C + (size_t)r0 * N + c0) = o0;
            *reinterpret_cast<float2*>(C + (size_t)r1 * N + c0) = o1;
        }
    }
}

// =====================================================================
// proj GEMM, 3xTF32 (near-fp32, unchanged from R7)
// =====================================================================
#define PBK 32
#define PJ_BM 128
#define PJ_ASTR 36
#define PJ_BSTR 100
#define PJ_A_WORDS (PJ_BM * PJ_ASTR)
#define PJ_B_WORDS (PBK * PJ_BSTR)
#define PJ_SMEM_BYTES ((2 * PJ_A_WORDS + 2 * PJ_B_WORDS) * 4)
#define PNK (D_ / PBK)

__global__ __launch_bounds__(256, 2)
void proj_gemm3x_kernel(const float* __restrict__ A,
                        const float* __restrict__ Whi,
                        const float* __restrict__ Wlo,
                        const float* __restrict__ bias,
                        float* __restrict__ C) {
    extern __shared__ uint32_t smemw[];
    uint32_t* Ahi = smemw;
    uint32_t* Alo = smemw + PJ_A_WORDS;
    uint32_t* Bhi = smemw + 2 * PJ_A_WORDS;
    uint32_t* Blo = smemw + 2 * PJ_A_WORDS + PJ_B_WORDS;

    const int tid  = threadIdx.x;
    const int lane = tid & 31;
    const int warp = tid >> 5;
    const int m0 = blockIdx.x * PJ_BM;

    const int warp_m = warp >> 2;
    const int warp_n = warp & 3;
    const int mBase = warp_m * 64;
    const int nBase = warp_n * 24;
    const int qr = lane >> 2;
    const int qc = lane & 3;

    const int aRow0 = tid >> 3;
    const int aC4   = (tid & 7) * 4;

    float4 aReg[4];
    float4 bhReg[3], blReg[3];

    auto gload = [&](int k0) {
        #pragma unroll
        for (int i = 0; i < 4; i++) {
            int arow = aRow0 + i * 32;
            aReg[i] = *reinterpret_cast<const float4*>(A + (size_t)(m0 + arow) * D_ + k0 + aC4);
        }
        #pragma unroll
        for (int i = 0; i < 3; i++) {
            int idx = tid + i * 256;
            int brow = idx / 24;
            int bc4  = (idx % 24) * 4;
            bhReg[i] = *reinterpret_cast<const float4*>(Whi + (size_t)(k0 + brow) * 96 + bc4);
            blReg[i] = *reinterpret_cast<const float4*>(Wlo + (size_t)(k0 + brow) * 96 + bc4);
        }
    };
    auto sstore = [&]() {
        #pragma unroll
        for (int i = 0; i < 4; i++) {
            int arow = aRow0 + i * 32;
            uint32_t* ph = Ahi + arow * PJ_ASTR + aC4;
            uint32_t* pl = Alo + arow * PJ_ASTR + aC4;
            float vv[4] = {aReg[i].x, aReg[i].y, aReg[i].z, aReg[i].w};
            #pragma unroll
            for (int j = 0; j < 4; j++) {
                uint32_t h = f2tf32(vv[j]);
                ph[j] = h;
                pl[j] = f2tf32(vv[j] - __uint_as_float(h));
            }
        }
        #pragma unroll
        for (int i = 0; i < 3; i++) {
            int idx = tid + i * 256;
            int brow = idx / 24;
            int bc4  = (idx % 24) * 4;
            *reinterpret_cast<float4*>(&Bhi[brow * PJ_BSTR + bc4]) = bhReg[i];
            *reinterpret_cast<float4*>(&Blo[brow * PJ_BSTR + bc4]) = blReg[i];
        }
    };

    float acc[4][3][4];
    #pragma unroll
    for (int i = 0; i < 4; i++)
        #pragma unroll
        for (int j = 0; j < 3; j++)
            #pragma unroll
            for (int r = 0; r < 4; r++) acc[i][j][r] = 0.f;

    gload(0);

    for (int it = 0; it < PNK; it++) {
        sstore();
        __syncthreads();
        if (it + 1 < PNK) gload((it + 1) * PBK);

        #pragma unroll
        for (int ks = 0; ks < 4; ks++) {
            const int kk = ks * 8;
            uint32_t bh0[3], bh1[3], bl0[3], bl1[3];
            #pragma unroll
            for (int nt = 0; nt < 3; nt++) {
                int col = nBase + nt * 8 + qr;
                bh0[nt] = Bhi[(kk + qc) * PJ_BSTR + col];
                bh1[nt] = Bhi[(kk + qc + 4) * PJ_BSTR + col];
                bl0[nt] = Blo[(kk + qc) * PJ_BSTR + col];
                bl1[nt] = Blo[(kk + qc + 4) * PJ_BSTR + col];
            }
            #pragma unroll
            for (int mt = 0; mt < 4; mt++) {
                int row = mBase + mt * 16 + qr;
                int i00 = row * PJ_ASTR + kk + qc;
                int i10 = (row + 8) * PJ_ASTR + kk + qc;
                uint32_t ah0 = Ahi[i00], ah1 = Ahi[i10];
                uint32_t ah2 = Ahi[i00 + 4], ah3 = Ahi[i10 + 4];
                uint32_t al0 = Alo[i00], al1 = Alo[i10];
                uint32_t al2 = Alo[i00 + 4], al3 = Alo[i10 + 4];
                #pragma unroll
                for (int nt = 0; nt < 3; nt++) {
                    mma_tf32(acc[mt][nt], ah0, ah1, ah2, ah3, bl0[nt], bl1[nt]);
                    mma_tf32(acc[mt][nt], al0, al1, al2, al3, bh0[nt], bh1[nt]);
                    mma_tf32(acc[mt][nt], ah0, ah1, ah2, ah3, bh0[nt], bh1[nt]);
                }
            }
        }
        __syncthreads();
    }

    #pragma unroll
    for (int mt = 0; mt < 4; mt++) {
        int r0 = m0 + mBase + mt * 16 + qr;
        int r1 = r0 + 8;
        #pragma unroll
        for (int nt = 0; nt < 3; nt++) {
            int c0 = nBase + nt * 8 + 2 * qc;
            float bb0 = bias[c0], bb1 = bias[c0 + 1];
            float2 o0 = make_float2(acc[mt][nt][0] + bb0, acc[mt][nt][1] + bb1);
            float2 o1 = make_float2(acc[mt][nt][2] + bb0, acc[mt][nt][3] + bb1);
            *reinterpret_cast<float2*>(C + (size_t)r0 * 96 + c0) = o0;
            *reinterpret_cast<float2*>(C + (size_t)r1 * 96 + c0) = o1;
        }
    }
}

// =====================================================================
// sampling: 8 rows per block (R14 best), float4 gathers. Chunk-local.
// =====================================================================
#define SROWS 8
__global__ __launch_bounds__(384)
void sample_kernel(const float* __restrict__ v,       // g_v chunk base
                   const float* __restrict__ offwt,   // chunk base
                   float4* __restrict__ attn) {       // chunk base
    __shared__ float row[SROWS][96];
    __shared__ int   sidx[SROWS][NH_][NP_][4];
    __shared__ float swg[SROWS][NH_][NP_][4];

    const int bl0 = blockIdx.x * SROWS;
    const int b = bl0 >> 12;
    const int t = threadIdx.x;

    // load 8 offwt rows (768 floats, 2/thread)
    #pragma unroll
    for (int i = 0; i < 2; i++) {
        int k = t + i * 384;
        row[k / 96][k % 96] = offwt[(size_t)bl0 * 96 + k];
    }
    __syncthreads();

    // setup: 256 items (8 rows x 8 heads x 4 points)
    if (t < SROWS * NH_ * NP_) {
        const int r  = t >> 5;
        const int hp = t & 31;
        const int hh = hp >> 2;
        const int p  = hp & 3;

        float lg[NP_];
        float m = -1e30f;
        #pragma unroll
        for (int q = 0; q < NP_; q++) { lg[q] = row[r][64 + hh * NP_ + q]; m = fmaxf(m, lg[q]); }
        float ssum = 0.f;
        #pragma unroll
        for (int q = 0; q < NP_; q++) ssum += __expf(lg[q] - m);
        const float s = __expf(lg[p] - m) / ssum;

        const int l = (bl0 + r) & (L_ - 1);
        const float off0 = row[r][hh * (NP_ * 2) + p * 2 + 0];
        const float off1 = row[r][hh * (NP_ * 2) + p * 2 + 1];
        const float gx = (float)(l & (GRID_ - 1)) * (1.f / (GRID_ - 1));
        const float gy = (float)(l >> 6)          * (1.f / (GRID_ - 1));
        const float ph = fminf(fmaxf(gx + off0, 0.f), 1.f) * (float)(GRID_ - 1);
        const float pw = fminf(fmaxf(gy + off1, 0.f), 1.f) * (float)(GRID_ - 1);
        const float y0f = floorf(ph), x0f = floorf(pw);
        const float wy = ph - y0f,    wx = pw - x0f;
        const int y0 = (int)y0f, x0 = (int)x0f;
        const int y1 = min(y0 + 1, GRID_ - 1);
        const int x1 = min(x0 + 1, GRID_ - 1);
        sidx[r][hh][p][0] = y0 * GRID_ + x0;  swg[r][hh][p][0] = s * (1.f - wy) * (1.f - wx);
        sidx[r][hh][p][1] = y0 * GRID_ + x1;  swg[r][hh][p][1] = s * (1.f - wy) * wx;
        sidx[r][hh][p][2] = y1 * GRID_ + x0;  swg[r][hh][p][2] = s * wy * (1.f - wx);
        sidx[r][hh][p][3] = y1 * GRID_ + x1;  swg[r][hh][p][3] = s * wy * wx;
    }
    __syncthreads();

    const int r0 = t / 96;          // 0..3
    const int c4 = t % 96;
    const int hh = c4 / 12;
    const int d4 = c4 % 12;

    const float4* vb = reinterpret_cast<const float4*>(v) + (size_t)b * L_ * 96 + hh * 12 + d4;

    #pragma unroll
    for (int rr = 0; rr < 2; rr++) {
        const int r = r0 + rr * 4;
        float4 acc = make_float4(0.f, 0.f, 0.f, 0.f);
        #pragma unroll
        for (int p = 0; p < NP_; p++) {
            #pragma unroll
            for (int c = 0; c < 4; c++) {
                const float w = swg[r][hh][p][c];
                const float4 vv = vb[(size_t)sidx[r][hh][p][c] * 96];
                acc.x += w * vv.x;
                acc.y += w * vv.y;
                acc.z += w * vv.z;
                acc.w += w * vv.w;
            }
        }
        float4 o;
        o.x = __uint_as_float(f2tf32(acc.x));
        o.y = __uint_as_float(f2tf32(acc.y));
        o.z = __uint_as_float(f2tf32(acc.z));
        o.w = __uint_as_float(f2tf32(acc.w));
        attn[(size_t)(bl0 + r) * 96 + c4] = o;
    }
}

// ---------------- streams/events (host-side only; created pre-main) ----------------
struct AsyncCtx {
    cudaStream_t sB = nullptr, sC = nullptr;
    cudaEvent_t evRoot = nullptr, evProj = nullptr, evWv = nullptr, evWo = nullptr;
    cudaEvent_t evG1[NCHUNK] = {}, evS[NCHUNK] = {};
    AsyncCtx() {
        cudaStreamCreateWithFlags(&sB, cudaStreamNonBlocking);
        cudaStreamCreateWithFlags(&sC, cudaStreamNonBlocking);
        cudaEventCreateWithFlags(&evRoot, cudaEventDisableTiming);
        cudaEventCreateWithFlags(&evProj, cudaEventDisableTiming);
        cudaEventCreateWithFlags(&evWv, cudaEventDisableTiming);
        cudaEventCreateWithFlags(&evWo, cudaEventDisableTiming);
        for (int i = 0; i < NCHUNK; i++) {
            cudaEventCreateWithFlags(&evG1[i], cudaEventDisableTiming);
            cudaEventCreateWithFlags(&evS[i], cudaEventDisableTiming);
        }
    }
};
static AsyncCtx g_async;

// ---------------- launch ----------------
extern "C" void kernel_launch(void* const* d_in, const int* in_sizes, int n_in,
                              void* d_out, int out_size) {
    const float* query = (const float*)d_in[0];
    const float* value = (const float*)d_in[2];
    const float* Wv   = (const float*)d_in[7];
    const float* bv   = (const float*)d_in[8];
    const float* Woff = (const float*)d_in[9];
    const float* boff = (const float*)d_in[10];
    const float* Wwt  = (const float*)d_in[11];
    const float* bwt  = (const float*)d_in[12];
    const float* Wo   = (const float*)d_in[13];
    const float* bo   = (const float*)d_in[14];
    float* out = (float*)d_out;

    float *gv, *gow, *gat, *gwv, *gwo, *gwh, *gwl, *gbp;
    cudaGetSymbolAddress((void**)&gv,  g_v);
    cudaGetSymbolAddress((void**)&gow, g_offwt);
    cudaGetSymbolAddress((void**)&gat, g_attn);
    cudaGetSymbolAddress((void**)&gwv, g_wv32);
    cudaGetSymbolAddress((void**)&gwo, g_wo32);
    cudaGetSymbolAddress((void**)&gwh, g_wpk_hi);
    cudaGetSymbolAddress((void**)&gwl, g_wpk_lo);
    cudaGetSymbolAddress((void**)&gbp, g_bpk);

    cudaFuncSetAttribute(gemm_tf32_kernel,
                         cudaFuncAttributeMaxDynamicSharedMemorySize, GEMM_SMEM_BYTES);
    cudaFuncSetAttribute(gemm_cvtA_kernel,
                         cudaFuncAttributeMaxDynamicSharedMemorySize, CA_SMEM_BYTES);
    cudaFuncSetAttribute(proj_gemm3x_kernel,
                         cudaFuncAttributeMaxDynamicSharedMemorySize, PJ_SMEM_BYTES);

    // ---- fork point ----
    cudaEventRecord(g_async.evRoot, 0);
    cudaStreamWaitEvent(g_async.sB, g_async.evRoot, 0);
    cudaStreamWaitEvent(g_async.sC, g_async.evRoot, 0);

    // ---- stream B (idle until sample): Wv + Wo cvts off the critical path ----
    cvt_tf32_kernel<<<72, 256, 0, g_async.sB>>>((const float4*)Wv, (float4*)gwv, (D_ * D_) / 4);
    cudaEventRecord(g_async.evWv, g_async.sB);
    cvt_tf32_kernel<<<72, 256, 0, g_async.sB>>>((const float4*)Wo, (float4*)gwo, (D_ * D_) / 4);
    cudaEventRecord(g_async.evWo, g_async.sB);

    // ---- stream C: proj path (evProj fires right after proj now) ----
    pack_projw_kernel<<<144, 256, 0, g_async.sC>>>(Woff, boff, Wwt, bwt, gwh, gwl, gbp);
    proj_gemm3x_kernel<<<M_ / PJ_BM, 256, PJ_SMEM_BYTES, g_async.sC>>>(query, gwh, gwl, gbp, gow);
    cudaEventRecord(g_async.evProj, g_async.sC);

    // ---- stream 0: G1 per chunk (waits Wv cvt) ----
    cudaStreamWaitEvent(0, g_async.evWv, 0);
    {
        dim3 grid(D_ / BN_, CHUNK_M / BM_);   // (3, 128) = 384 CTAs per chunk
        for (int i = 0; i < NCHUNK; i++) {
            size_t off = (size_t)i * CHUNK_M * D_;
            gemm_cvtA_kernel<<<grid, 256, CA_SMEM_BYTES>>>(value + off, gwv, bv, gv + off,
                                                           CHUNK_M, D_, D_);
            cudaEventRecord(g_async.evG1[i], 0);
        }
    }

    // ---- stream B: sample per chunk ----
    cudaStreamWaitEvent(g_async.sB, g_async.evProj, 0);
    for (int i = 0; i < NCHUNK; i++) {
        cudaStreamWaitEvent(g_async.sB, g_async.evG1[i], 0);
        size_t voff = (size_t)i * CHUNK_M * D_;
        size_t ooff = (size_t)i * CHUNK_M * 96;
        sample_kernel<<<CHUNK_M / SROWS, 384, 0, g_async.sB>>>(gv + voff, gow + ooff,
                                                               (float4*)(gat + voff));
        cudaEventRecord(g_async.evS[i], g_async.sB);
    }

    // ---- stream 0: G2 per chunk (waits Wo cvt once); joins all branches ----
    cudaStreamWaitEvent(0, g_async.evWo, 0);
    {
        dim3 grid(D_ / BN_, CHUNK_M / BM_);
        for (int i = 0; i < NCHUNK; i++) {
            cudaStreamWaitEvent(0, g_async.evS[i], 0);
            size_t off = (size_t)i * CHUNK_M * D_;
            gemm_tf32_kernel<<<grid, 256, GEMM_SMEM_BYTES>>>(gat + off, gwo, bo, out + off,
                                                             CHUNK_M, D_, D_);
        }
    }
}